// round 1
// baseline (speedup 1.0000x reference)
#include <cuda_runtime.h>

#define BATCH    32768
#define IN_DIM   256
#define HID      512
#define OUT_DIM  128
#define NSTEPS   40
#define MT       32          // batch rows per CTA
#define NTHREADS 256
#define DRV_PITCH 513        // +1 float pad: row-to-row bank shift of 1

#define SMEM_FLOATS (HID * MT + 2 * MT * DRV_PITCH + HID)

// C = A(s_t, K-major [K][MT]) x B(gmem row-major [N][K])^T  microtile 4x16
template <int K>
__device__ __forceinline__ void gemm_tile(const float* __restrict__ As,
                                          const float* __restrict__ Bg,
                                          int row0, int col0,
                                          float acc[4][16]) {
#pragma unroll
  for (int i = 0; i < 4; i++)
#pragma unroll
    for (int j = 0; j < 16; j++) acc[i][j] = 0.f;

#pragma unroll 1
  for (int k = 0; k < K; k += 4) {
    float4 a[4];
#pragma unroll
    for (int kk = 0; kk < 4; kk++)
      a[kk] = *reinterpret_cast<const float4*>(As + (k + kk) * MT + row0);
    float4 bb[16];
#pragma unroll
    for (int j = 0; j < 16; j++)
      bb[j] = *reinterpret_cast<const float4*>(Bg + (size_t)(col0 + j) * K + k);
#pragma unroll
    for (int j = 0; j < 16; j++) {
      float bv[4] = {bb[j].x, bb[j].y, bb[j].z, bb[j].w};
#pragma unroll
      for (int kk = 0; kk < 4; kk++) {
        acc[0][j] = fmaf(a[kk].x, bv[kk], acc[0][j]);
        acc[1][j] = fmaf(a[kk].y, bv[kk], acc[1][j]);
        acc[2][j] = fmaf(a[kk].z, bv[kk], acc[2][j]);
        acc[3][j] = fmaf(a[kk].w, bv[kk], acc[3][j]);
      }
    }
  }
}

__global__ void __launch_bounds__(NTHREADS, 1)
liq_kernel(const float* __restrict__ x,   const float* __restrict__ Wx,
           const float* __restrict__ bx,  const float* __restrict__ W,
           const float* __restrict__ U,   const float* __restrict__ bvec,
           const float* __restrict__ tau, const float* __restrict__ Wf,
           const float* __restrict__ bf,  float* __restrict__ out) {
  extern __shared__ float smem[];
  float* s_t  = smem;                       // [HID][MT]  stage value, K-major
  float* drv  = smem + HID * MT;            // [MT][DRV_PITCH] constant drive
  float* hn_s = drv + MT * DRV_PITCH;       // [MT][DRV_PITCH] RK4 accumulator
  float* itau = hn_s + MT * DRV_PITCH;      // [HID] 1/tau
  float* xs   = drv;                        // overlay: x tile lives here in phase 0

  const int tid  = threadIdx.x;
  const int tm   = tid & 7;                 // 8 row groups
  const int tn   = tid >> 3;                // 32 col groups
  const int row0 = tm * 4;
  const int col0 = tn * 16;
  const int b0   = blockIdx.x * MT;

  for (int i = tid; i < HID; i += NTHREADS) itau[i] = 1.f / tau[i];

  // stage x tile transposed: xs[k][m]
  for (int idx = tid; idx < MT * IN_DIM; idx += NTHREADS) {
    int m = idx >> 8;                       // IN_DIM == 256
    int k = idx & (IN_DIM - 1);
    xs[k * MT + m] = x[(size_t)(b0 + m) * IN_DIM + k];
  }
  __syncthreads();

  float h[4][16], acc[4][16];

  // phase 0: u = x @ Wx^T + bx   (h0 = u)
  gemm_tile<IN_DIM>(xs, Wx, row0, col0, acc);
#pragma unroll
  for (int j = 0; j < 16; j++) {
    float bxi = bx[col0 + j];
#pragma unroll
    for (int i = 0; i < 4; i++) h[i][j] = acc[i][j] + bxi;
  }
  __syncthreads();  // all xs reads complete before drv (alias) is written later
#pragma unroll
  for (int j = 0; j < 16; j++)
    *reinterpret_cast<float4*>(s_t + (col0 + j) * MT + row0) =
        make_float4(h[0][j], h[1][j], h[2][j], h[3][j]);
  __syncthreads();

  // phase 1: drive = u @ U^T + b
  gemm_tile<HID>(s_t, U, row0, col0, acc);
#pragma unroll
  for (int j = 0; j < 16; j++) {
    float bj = bvec[col0 + j];
#pragma unroll
    for (int i = 0; i < 4; i++)
      drv[(row0 + i) * DRV_PITCH + col0 + j] = acc[i][j] + bj;
  }
  __syncthreads();

  const float dt = (1.0f - 0.0f) / NSTEPS;

  // 40 RK4 steps; invariant: s_t holds current stage input (starts as h)
#pragma unroll 1
  for (int step = 0; step < NSTEPS; step++) {
#pragma unroll
    for (int st = 0; st < 4; st++) {
      gemm_tile<HID>(s_t, W, row0, col0, acc);
      const float wgt = (st == 0 || st == 3) ? (dt / 6.f) : (dt / 3.f);
#pragma unroll
      for (int j = 0; j < 16; j++) {
        const int n = col0 + j;
        const float it = itau[n];
#pragma unroll
        for (int i = 0; i < 4; i++) {
          const int m = row0 + i;
          float sv  = s_t[n * MT + m];                       // stage input value
          float a   = acc[i][j] + drv[m * DRV_PITCH + n];
          float kv  = (tanhf(a) - sv) * it;                  // f(s) component
          float hni = (st == 0 ? h[i][j] : hn_s[m * DRV_PITCH + n]) + wgt * kv;
          hn_s[m * DRV_PITCH + n] = hni;
          if (st == 0 || st == 1)
            acc[i][j] = h[i][j] + 0.5f * dt * kv;            // next stage value
          else if (st == 2)
            acc[i][j] = h[i][j] + dt * kv;
          else {
            h[i][j] = hni;                                   // commit h_{n+1}
            acc[i][j] = hni;                                 // s_t := h for next step
          }
        }
      }
      __syncthreads();   // all GEMM reads of s_t done before overwrite
#pragma unroll
      for (int j = 0; j < 16; j++)
        *reinterpret_cast<float4*>(s_t + (col0 + j) * MT + row0) =
            make_float4(acc[0][j], acc[1][j], acc[2][j], acc[3][j]);
      __syncthreads();
    }
  }

  // head: out = h @ Wf^T + bf   (s_t holds final h)
  float acc2[4][4];
#pragma unroll
  for (int i = 0; i < 4; i++)
#pragma unroll
    for (int j = 0; j < 4; j++) acc2[i][j] = 0.f;
  const int oc0 = tn * 4;
#pragma unroll 1
  for (int k = 0; k < HID; k += 4) {
    float4 a[4];
#pragma unroll
    for (int kk = 0; kk < 4; kk++)
      a[kk] = *reinterpret_cast<const float4*>(s_t + (k + kk) * MT + row0);
#pragma unroll
    for (int j = 0; j < 4; j++) {
      float4 bb = *reinterpret_cast<const float4*>(Wf + (size_t)(oc0 + j) * HID + k);
      float bv[4] = {bb.x, bb.y, bb.z, bb.w};
#pragma unroll
      for (int kk = 0; kk < 4; kk++) {
        acc2[0][j] = fmaf(a[kk].x, bv[kk], acc2[0][j]);
        acc2[1][j] = fmaf(a[kk].y, bv[kk], acc2[1][j]);
        acc2[2][j] = fmaf(a[kk].z, bv[kk], acc2[2][j]);
        acc2[3][j] = fmaf(a[kk].w, bv[kk], acc2[3][j]);
      }
    }
  }
#pragma unroll
  for (int i = 0; i < 4; i++) {
    float4 o = make_float4(acc2[i][0] + bf[oc0 + 0], acc2[i][1] + bf[oc0 + 1],
                           acc2[i][2] + bf[oc0 + 2], acc2[i][3] + bf[oc0 + 3]);
    *reinterpret_cast<float4*>(out + (size_t)(b0 + row0 + i) * OUT_DIM + oc0) = o;
  }
}

extern "C" void kernel_launch(void* const* d_in, const int* in_sizes, int n_in,
                              void* d_out, int out_size) {
  (void)in_sizes; (void)n_in; (void)out_size;
  const float* x    = (const float*)d_in[0];
  const float* Wx   = (const float*)d_in[1];
  const float* bx   = (const float*)d_in[2];
  const float* W    = (const float*)d_in[3];
  const float* U    = (const float*)d_in[4];
  const float* bvec = (const float*)d_in[5];
  const float* tau  = (const float*)d_in[6];
  const float* Wf   = (const float*)d_in[7];
  const float* bf   = (const float*)d_in[8];
  float* out = (float*)d_out;

  size_t smem_bytes = (size_t)SMEM_FLOATS * sizeof(float);
  cudaFuncSetAttribute(liq_kernel, cudaFuncAttributeMaxDynamicSharedMemorySize,
                       (int)smem_bytes);
  liq_kernel<<<BATCH / MT, NTHREADS, smem_bytes>>>(x, Wx, bx, W, U, bvec, tau,
                                                   Wf, bf, out);
}

// round 3
// speedup vs baseline: 1.5371x; 1.5371x over previous
#include <cuda_runtime.h>
#include <cuda_bf16.h>
#include <cstdint>

#define BATCH    32768
#define IN_DIM   256
#define HID      512
#define OUT_DIM  128
#define NSTEPS   40
#define DT       0.025f
#define HDT      0.0125f
#define DT6      (0.025f / 6.0f)

// ---------------- static device scratch ----------------
__device__ __align__(128) __nv_bfloat16 g_S0h[(size_t)BATCH * HID];
__device__ __align__(128) __nv_bfloat16 g_S0l[(size_t)BATCH * HID];
__device__ __align__(128) __nv_bfloat16 g_S1h[(size_t)BATCH * HID];
__device__ __align__(128) __nv_bfloat16 g_S1l[(size_t)BATCH * HID];
__device__ __align__(128) __nv_bfloat16 g_S2h[(size_t)BATCH * HID];
__device__ __align__(128) __nv_bfloat16 g_S2l[(size_t)BATCH * HID];
__device__ __align__(128) __nv_bfloat16 g_S3h[(size_t)BATCH * HID];
__device__ __align__(128) __nv_bfloat16 g_S3l[(size_t)BATCH * HID];
__device__ __align__(128) __nv_bfloat16 g_Wbig[(size_t)HID * 1536];  // [n][k']: Whi|Whi|Wlo
__device__ __align__(128) float g_u[(size_t)BATCH * HID];
__device__ __align__(128) float g_drive[(size_t)BATCH * HID];
__device__ __align__(128) float g_itau[HID];

__device__ __forceinline__ __nv_bfloat16* Sh_ptr(int i) {
  switch (i) { case 0: return g_S0h; case 1: return g_S1h; case 2: return g_S2h; default: return g_S3h; }
}
__device__ __forceinline__ __nv_bfloat16* Sl_ptr(int i) {
  switch (i) { case 0: return g_S0l; case 1: return g_S1l; case 2: return g_S2l; default: return g_S3l; }
}

// ---------------- helpers ----------------
__device__ __forceinline__ uint32_t smem_u32(const void* p) {
  uint32_t a;
  asm("{ .reg .u64 t; cvta.to.shared.u64 t, %1; cvt.u32.u64 %0, t; }" : "=r"(a) : "l"(p));
  return a;
}
__device__ __forceinline__ void cp16(uint32_t dst, const void* src) {
  asm volatile("cp.async.cg.shared.global [%0], [%1], 16;" :: "r"(dst), "l"(src) : "memory");
}
#define CP_COMMIT() asm volatile("cp.async.commit_group;" ::: "memory")
#define CP_WAIT0()  asm volatile("cp.async.wait_group 0;" ::: "memory")

#define LDSM4(r0, r1, r2, r3, a) \
  asm volatile("ldmatrix.sync.aligned.m8n8.x4.shared.b16 {%0,%1,%2,%3}, [%4];" \
               : "=r"(r0), "=r"(r1), "=r"(r2), "=r"(r3) : "r"(a))

#define MMA16816(d, a, b0, b1) \
  asm volatile("mma.sync.aligned.m16n8k16.row.col.f32.bf16.bf16.f32 " \
               "{%0,%1,%2,%3},{%4,%5,%6,%7},{%8,%9},{%0,%1,%2,%3};" \
               : "+f"((d)[0]), "+f"((d)[1]), "+f"((d)[2]), "+f"((d)[3]) \
               : "r"((a)[0]), "r"((a)[1]), "r"((a)[2]), "r"((a)[3]), "r"(b0), "r"(b1))

__device__ __forceinline__ float tanh_fast(float x) {
  float e = __expf(2.0f * x);
  return 1.0f - __fdividef(2.0f, e + 1.0f);
}

// ---------------- prep: W -> [Whi | Whi | Wlo] bf16, itau ----------------
__global__ void k_prep_w(const float* __restrict__ W, const float* __restrict__ tau) {
  int idx = blockIdx.x * 256 + threadIdx.x;           // 512*1536 total
  int n = idx / 1536, k = idx % 1536;
  int kk = k & 511, region = k >> 9;
  float w = W[n * 512 + kk];
  __nv_bfloat16 hi = __float2bfloat16(w);
  g_Wbig[idx] = (region < 2) ? hi : __float2bfloat16(w - __bfloat162float(hi));
  if (idx < HID) g_itau[idx] = 1.0f / tau[idx];
}

// ---------------- fp32 microtile GEMM (prologue/head) ----------------
template <int K>
__device__ __forceinline__ void gemm_tile(const float* __restrict__ As,
                                          const float* __restrict__ Bg,
                                          int row0, int col0, float acc[4][16]) {
#pragma unroll
  for (int i = 0; i < 4; i++)
#pragma unroll
    for (int j = 0; j < 16; j++) acc[i][j] = 0.f;
#pragma unroll 1
  for (int k = 0; k < K; k += 4) {
    float4 a[4];
#pragma unroll
    for (int kk = 0; kk < 4; kk++)
      a[kk] = *reinterpret_cast<const float4*>(As + (k + kk) * 32 + row0);
    float4 bb[16];
#pragma unroll
    for (int j = 0; j < 16; j++)
      bb[j] = *reinterpret_cast<const float4*>(Bg + (size_t)(col0 + j) * K + k);
#pragma unroll
    for (int j = 0; j < 16; j++) {
      float bv[4] = {bb[j].x, bb[j].y, bb[j].z, bb[j].w};
#pragma unroll
      for (int kk = 0; kk < 4; kk++) {
        acc[0][j] = fmaf(a[kk].x, bv[kk], acc[0][j]);
        acc[1][j] = fmaf(a[kk].y, bv[kk], acc[1][j]);
        acc[2][j] = fmaf(a[kk].z, bv[kk], acc[2][j]);
        acc[3][j] = fmaf(a[kk].w, bv[kk], acc[3][j]);
      }
    }
  }
}

// u = x @ Wx^T + bx ; writes g_u and S0 (h0 = u)
__global__ void __launch_bounds__(256, 1)
k_in(const float* __restrict__ x, const float* __restrict__ Wx,
     const float* __restrict__ bx) {
  extern __shared__ float sm[];
  const int tid = threadIdx.x, b0 = blockIdx.x * 32;
  for (int idx = tid; idx < 32 * IN_DIM; idx += 256) {
    int m = idx >> 8, k = idx & 255;
    sm[k * 32 + m] = x[(size_t)(b0 + m) * IN_DIM + k];
  }
  __syncthreads();
  const int row0 = (tid & 7) * 4, col0 = (tid >> 3) * 16;
  float acc[4][16];
  gemm_tile<IN_DIM>(sm, Wx, row0, col0, acc);
#pragma unroll
  for (int j = 0; j < 16; j++) {
    float bxi = bx[col0 + j];
#pragma unroll
    for (int i = 0; i < 4; i++) {
      float v = acc[i][j] + bxi;
      size_t ix = (size_t)(b0 + row0 + i) * HID + col0 + j;
      g_u[ix] = v;
      __nv_bfloat16 hi = __float2bfloat16(v);
      g_S0h[ix] = hi;
      g_S0l[ix] = __float2bfloat16(v - __bfloat162float(hi));
    }
  }
}

// drive = u @ U^T + b
__global__ void __launch_bounds__(256, 1)
k_drive(const float* __restrict__ U, const float* __restrict__ bvec) {
  extern __shared__ float sm[];
  const int tid = threadIdx.x, b0 = blockIdx.x * 32;
  for (int idx = tid; idx < 32 * HID; idx += 256) {
    int m = idx >> 9, k = idx & 511;
    sm[k * 32 + m] = g_u[(size_t)(b0 + m) * HID + k];
  }
  __syncthreads();
  const int row0 = (tid & 7) * 4, col0 = (tid >> 3) * 16;
  float acc[4][16];
  gemm_tile<HID>(sm, U, row0, col0, acc);
#pragma unroll
  for (int j = 0; j < 16; j++) {
    float bj = bvec[col0 + j];
#pragma unroll
    for (int i = 0; i < 4; i++)
      g_drive[(size_t)(b0 + row0 + i) * HID + col0 + j] = acc[i][j] + bj;
  }
}

// out = h @ Wf^T + bf  (h = S0 hi+lo)
__global__ void __launch_bounds__(256, 1)
k_head(const float* __restrict__ Wf, const float* __restrict__ bf,
       float* __restrict__ out) {
  extern __shared__ float sm[];
  const int tid = threadIdx.x, b0 = blockIdx.x * 32;
  for (int idx = tid; idx < 32 * HID; idx += 256) {
    int m = idx >> 9, k = idx & 511;
    size_t ix = (size_t)(b0 + m) * HID + k;
    sm[k * 32 + m] = __bfloat162float(g_S0h[ix]) + __bfloat162float(g_S0l[ix]);
  }
  __syncthreads();
  const int row0 = (tid & 7) * 4, oc0 = (tid >> 3) * 4;
  float acc[4][4];
#pragma unroll
  for (int i = 0; i < 4; i++)
#pragma unroll
    for (int j = 0; j < 4; j++) acc[i][j] = 0.f;
#pragma unroll 1
  for (int k = 0; k < HID; k += 4) {
    float4 a[4];
#pragma unroll
    for (int kk = 0; kk < 4; kk++)
      a[kk] = *reinterpret_cast<const float4*>(sm + (k + kk) * 32 + row0);
#pragma unroll
    for (int j = 0; j < 4; j++) {
      float4 bb = *reinterpret_cast<const float4*>(Wf + (size_t)(oc0 + j) * HID + k);
      float bv[4] = {bb.x, bb.y, bb.z, bb.w};
#pragma unroll
      for (int kk = 0; kk < 4; kk++) {
        acc[0][j] = fmaf(a[kk].x, bv[kk], acc[0][j]);
        acc[1][j] = fmaf(a[kk].y, bv[kk], acc[1][j]);
        acc[2][j] = fmaf(a[kk].z, bv[kk], acc[2][j]);
        acc[3][j] = fmaf(a[kk].w, bv[kk], acc[3][j]);
      }
    }
  }
#pragma unroll
  for (int i = 0; i < 4; i++) {
    float4 o = make_float4(acc[i][0] + bf[oc0 + 0], acc[i][1] + bf[oc0 + 1],
                           acc[i][2] + bf[oc0 + 2], acc[i][3] + bf[oc0 + 3]);
    *reinterpret_cast<float4*>(out + (size_t)(b0 + row0 + i) * OUT_DIM + oc0) = o;
  }
}

// ---------------- stage kernel: mma.sync GEMM + fused RK4 epilogue ----------------
// SMEM: A bufs 2 x (128 rows x 144B), B bufs 2 x (128 rows x 144B)
#define APITCH   144
#define ABUF(b)  ((b) * 18432)
#define BBUF(b)  (36864 + (b) * 18432)
#define ST_SMEM  73728

__device__ __forceinline__ void ld_chunk(uint32_t sb, int buf, int b0, int n0, int kc,
                                         int tid, const __nv_bfloat16* shi,
                                         const __nv_bfloat16* slo) {
  const int region = kc >> 3;
  const __nv_bfloat16* asrc = (region == 1) ? slo : shi;
  const int k0 = (kc & 7) << 6;          // col offset within S (elements)
  const int kg = kc << 6;                // col offset within Wbig (elements)
  const uint32_t abase = sb + ABUF(buf);
  const uint32_t bbase = sb + BBUF(buf);
#pragma unroll
  for (int j = 0; j < 4; j++) {
    int idx = tid + j * 256;
    int r = idx >> 3, c = idx & 7;       // 128 rows x 8 x 16B
    cp16(abase + r * APITCH + c * 16, asrc + (((size_t)(b0 + r)) << 9) + k0 + c * 8);
    cp16(bbase + r * APITCH + c * 16, g_Wbig + (size_t)(n0 + r) * 1536 + kg + c * 8);
  }
}

template <int ST>
__global__ void __launch_bounds__(256, 1) k_stage() {
  extern __shared__ __align__(128) char smem[];
  const uint32_t sb = smem_u32(smem);
  const int tid = threadIdx.x;
  const int lane = tid & 31, wid = tid >> 5;
  const int warp_m = wid & 3;            // 4 warps along M (32 rows each)
  const int warp_n = wid >> 2;           // 2 warps along N (64 cols each)
  const int b0 = blockIdx.x * 128;
  const int lr = lane & 15, lc = lane >> 4;   // ldmatrix addressing

  const __nv_bfloat16* shi = Sh_ptr(ST);
  const __nv_bfloat16* slo = Sl_ptr(ST);
  __nv_bfloat16* dsth = Sh_ptr((ST + 1) & 3);
  __nv_bfloat16* dstl = Sl_ptr((ST + 1) & 3);

#pragma unroll 1
  for (int nc = 0; nc < 4; ++nc) {
    const int n0 = nc * 128;
    float acc[2][8][4];
#pragma unroll
    for (int i = 0; i < 2; i++)
#pragma unroll
      for (int j = 0; j < 8; j++)
#pragma unroll
        for (int q = 0; q < 4; q++) acc[i][j][q] = 0.f;

    ld_chunk(sb, 0, b0, n0, 0, tid, shi, slo);
    CP_COMMIT();
    CP_WAIT0();
    __syncthreads();

#pragma unroll 1
    for (int kc = 0; kc < 24; ++kc) {
      const int buf = kc & 1;
      if (kc < 23) { ld_chunk(sb, buf ^ 1, b0, n0, kc + 1, tid, shi, slo); CP_COMMIT(); }

      const uint32_t ab = sb + ABUF(buf) + (warp_m * 32 + lr) * APITCH + lc * 16;
      const uint32_t bb = sb + BBUF(buf) + (warp_n * 64 + lr) * APITCH + lc * 16;
#pragma unroll
      for (int kk = 0; kk < 4; kk++) {
        uint32_t a0[4], a1[4];
        LDSM4(a0[0], a0[1], a0[2], a0[3], ab + kk * 32);
        LDSM4(a1[0], a1[1], a1[2], a1[3], ab + 16 * APITCH + kk * 32);
        uint32_t bF[4][4];
#pragma unroll
        for (int fnp = 0; fnp < 4; fnp++)
          LDSM4(bF[fnp][0], bF[fnp][1], bF[fnp][2], bF[fnp][3],
                bb + fnp * 16 * APITCH + kk * 32);
#pragma unroll
        for (int fnp = 0; fnp < 4; fnp++) {
          MMA16816(acc[0][2 * fnp],     a0, bF[fnp][0], bF[fnp][2]);
          MMA16816(acc[0][2 * fnp + 1], a0, bF[fnp][1], bF[fnp][3]);
          MMA16816(acc[1][2 * fnp],     a1, bF[fnp][0], bF[fnp][2]);
          MMA16816(acc[1][2 * fnp + 1], a1, bF[fnp][1], bF[fnp][3]);
        }
      }
      CP_WAIT0();
      __syncthreads();
    }

    // ---- fused RK4 epilogue on register fragments ----
    const int rq = lane >> 2, cq = (lane & 3) * 2;
#pragma unroll
    for (int fn = 0; fn < 8; fn++) {
      const int nn = n0 + warp_n * 64 + fn * 8 + cq;
      const float2 it2 = *reinterpret_cast<const float2*>(g_itau + nn);
#pragma unroll
      for (int fm = 0; fm < 2; fm++) {
#pragma unroll
        for (int half = 0; half < 2; half++) {
          const int r = b0 + warp_m * 32 + fm * 16 + rq + half * 8;
          const size_t ix = ((size_t)r << 9) + nn;
          const float c0 = acc[fm][fn][half * 2];
          const float c1 = acc[fm][fn][half * 2 + 1];
          float2 dr = *reinterpret_cast<const float2*>(g_drive + ix);
          __nv_bfloat162 sh2 = *reinterpret_cast<const __nv_bfloat162*>(shi + ix);
          __nv_bfloat162 sl2 = *reinterpret_cast<const __nv_bfloat162*>(slo + ix);
          float s0 = __bfloat162float(sh2.x) + __bfloat162float(sl2.x);
          float s1 = __bfloat162float(sh2.y) + __bfloat162float(sl2.y);
          float t0 = tanh_fast(c0 + dr.x);
          float t1 = tanh_fast(c1 + dr.y);
          float k0 = (t0 - s0) * it2.x;
          float k1 = (t1 - s1) * it2.y;
          float v0, v1;
          if (ST == 0) {
            v0 = s0 + HDT * k0; v1 = s1 + HDT * k1;       // s2 = h + dt/2 k1
          } else {
            __nv_bfloat162 hh2 = *reinterpret_cast<const __nv_bfloat162*>(g_S0h + ix);
            __nv_bfloat162 hl2 = *reinterpret_cast<const __nv_bfloat162*>(g_S0l + ix);
            float h0 = __bfloat162float(hh2.x) + __bfloat162float(hl2.x);
            float h1 = __bfloat162float(hh2.y) + __bfloat162float(hl2.y);
            if (ST == 1) {
              v0 = h0 + HDT * k0; v1 = h1 + HDT * k1;     // s3
            } else if (ST == 2) {
              v0 = h0 + DT * k0;  v1 = h1 + DT * k1;      // s4
            } else {
              __nv_bfloat162 ah2 = *reinterpret_cast<const __nv_bfloat162*>(g_S1h + ix);
              __nv_bfloat162 al2 = *reinterpret_cast<const __nv_bfloat162*>(g_S1l + ix);
              __nv_bfloat162 bh2 = *reinterpret_cast<const __nv_bfloat162*>(g_S2h + ix);
              __nv_bfloat162 bl2 = *reinterpret_cast<const __nv_bfloat162*>(g_S2l + ix);
              float s20 = __bfloat162float(ah2.x) + __bfloat162float(al2.x);
              float s21 = __bfloat162float(ah2.y) + __bfloat162float(al2.y);
              float s30 = __bfloat162float(bh2.x) + __bfloat162float(bl2.x);
              float s31 = __bfloat162float(bh2.y) + __bfloat162float(bl2.y);
              v0 = h0 + (1.0f / 3.0f) * (s20 - h0) + (2.0f / 3.0f) * (s30 - h0)
                      + (1.0f / 3.0f) * (s0 - h0) + DT6 * k0;   // h_{n+1}
              v1 = h1 + (1.0f / 3.0f) * (s21 - h1) + (2.0f / 3.0f) * (s31 - h1)
                      + (1.0f / 3.0f) * (s1 - h1) + DT6 * k1;
            }
          }
          __nv_bfloat16 hi0 = __float2bfloat16(v0);
          __nv_bfloat16 hi1 = __float2bfloat16(v1);
          __nv_bfloat162 oh; oh.x = hi0; oh.y = hi1;
          __nv_bfloat162 ol;
          ol.x = __float2bfloat16(v0 - __bfloat162float(hi0));
          ol.y = __float2bfloat16(v1 - __bfloat162float(hi1));
          *reinterpret_cast<__nv_bfloat162*>(dsth + ix) = oh;
          *reinterpret_cast<__nv_bfloat162*>(dstl + ix) = ol;
        }
      }
    }
    __syncthreads();   // buffers reused next n_chunk
  }
}

// ---------------- launcher ----------------
extern "C" void kernel_launch(void* const* d_in, const int* in_sizes, int n_in,
                              void* d_out, int out_size) {
  (void)in_sizes; (void)n_in; (void)out_size;
  const float* x    = (const float*)d_in[0];
  const float* Wx   = (const float*)d_in[1];
  const float* bx   = (const float*)d_in[2];
  const float* W    = (const float*)d_in[3];
  const float* U    = (const float*)d_in[4];
  const float* bvec = (const float*)d_in[5];
  const float* tau  = (const float*)d_in[6];
  const float* Wf   = (const float*)d_in[7];
  const float* bf   = (const float*)d_in[8];
  float* out = (float*)d_out;

  cudaFuncSetAttribute(k_stage<0>, cudaFuncAttributeMaxDynamicSharedMemorySize, ST_SMEM);
  cudaFuncSetAttribute(k_stage<1>, cudaFuncAttributeMaxDynamicSharedMemorySize, ST_SMEM);
  cudaFuncSetAttribute(k_stage<2>, cudaFuncAttributeMaxDynamicSharedMemorySize, ST_SMEM);
  cudaFuncSetAttribute(k_stage<3>, cudaFuncAttributeMaxDynamicSharedMemorySize, ST_SMEM);
  cudaFuncSetAttribute(k_drive, cudaFuncAttributeMaxDynamicSharedMemorySize, 65536);
  cudaFuncSetAttribute(k_head,  cudaFuncAttributeMaxDynamicSharedMemorySize, 65536);
  cudaFuncSetAttribute(k_in,    cudaFuncAttributeMaxDynamicSharedMemorySize, 32768);

  k_prep_w<<<(512 * 1536) / 256, 256>>>(W, tau);
  k_in<<<BATCH / 32, 256, 32768>>>(x, Wx, bx);
  k_drive<<<BATCH / 32, 256, 65536>>>(U, bvec);
  for (int step = 0; step < NSTEPS; ++step) {
    k_stage<0><<<BATCH / 128, 256, ST_SMEM>>>();
    k_stage<1><<<BATCH / 128, 256, ST_SMEM>>>();
    k_stage<2><<<BATCH / 128, 256, ST_SMEM>>>();
    k_stage<3><<<BATCH / 128, 256, ST_SMEM>>>();
  }
  k_head<<<BATCH / 32, 256, 65536>>>(Wf, bf, out);
}

// round 4
// speedup vs baseline: 1.8053x; 1.1745x over previous
#include <cuda_runtime.h>
#include <cuda_bf16.h>
#include <cstdint>

#define BATCH    32768
#define IN_DIM   256
#define HID      512
#define OUT_DIM  128
#define NSTEPS   40
#define DT       0.025f
#define HDT      0.0125f
#define DT6      (0.025f / 6.0f)

// ---------------- static device scratch ----------------
__device__ __align__(128) __nv_bfloat16 g_S0h[(size_t)BATCH * HID];
__device__ __align__(128) __nv_bfloat16 g_S0l[(size_t)BATCH * HID];
__device__ __align__(128) __nv_bfloat16 g_S1h[(size_t)BATCH * HID];
__device__ __align__(128) __nv_bfloat16 g_S1l[(size_t)BATCH * HID];
__device__ __align__(128) __nv_bfloat16 g_S2h[(size_t)BATCH * HID];
__device__ __align__(128) __nv_bfloat16 g_S2l[(size_t)BATCH * HID];
__device__ __align__(128) __nv_bfloat16 g_S3h[(size_t)BATCH * HID];
__device__ __align__(128) __nv_bfloat16 g_S3l[(size_t)BATCH * HID];
__device__ __align__(128) __nv_bfloat16 g_Wbig[(size_t)HID * 1536];  // [n][k']: Whi|Whi|Wlo
__device__ __align__(128) __nv_bfloat16 g_Ubig[(size_t)HID * 1536];  // [n][k']: Uhi|Uhi|Ulo
__device__ __align__(128) float g_drive[(size_t)BATCH * HID];
__device__ __align__(128) float g_itau[HID];

__device__ __forceinline__ __nv_bfloat16* Sh_ptr(int i) {
  switch (i) { case 0: return g_S0h; case 1: return g_S1h; case 2: return g_S2h; default: return g_S3h; }
}
__device__ __forceinline__ __nv_bfloat16* Sl_ptr(int i) {
  switch (i) { case 0: return g_S0l; case 1: return g_S1l; case 2: return g_S2l; default: return g_S3l; }
}

// ---------------- helpers ----------------
__device__ __forceinline__ uint32_t smem_u32(const void* p) {
  uint32_t a;
  asm("{ .reg .u64 t; cvta.to.shared.u64 t, %1; cvt.u32.u64 %0, t; }" : "=r"(a) : "l"(p));
  return a;
}
__device__ __forceinline__ void cp16(uint32_t dst, const void* src) {
  asm volatile("cp.async.cg.shared.global [%0], [%1], 16;" :: "r"(dst), "l"(src) : "memory");
}
#define CP_COMMIT() asm volatile("cp.async.commit_group;" ::: "memory")
#define CP_WAIT1()  asm volatile("cp.async.wait_group 1;" ::: "memory")

#define LDSM4(r0, r1, r2, r3, a) \
  asm volatile("ldmatrix.sync.aligned.m8n8.x4.shared.b16 {%0,%1,%2,%3}, [%4];" \
               : "=r"(r0), "=r"(r1), "=r"(r2), "=r"(r3) : "r"(a))

#define MMA16816(d, a, b0, b1) \
  asm volatile("mma.sync.aligned.m16n8k16.row.col.f32.bf16.bf16.f32 " \
               "{%0,%1,%2,%3},{%4,%5,%6,%7},{%8,%9},{%0,%1,%2,%3};" \
               : "+f"((d)[0]), "+f"((d)[1]), "+f"((d)[2]), "+f"((d)[3]) \
               : "r"((a)[0]), "r"((a)[1]), "r"((a)[2]), "r"((a)[3]), "r"(b0), "r"(b1))

__device__ __forceinline__ float tanh_fast(float x) {
  float e = __expf(2.0f * x);
  return 1.0f - __fdividef(2.0f, e + 1.0f);
}

// ---------------- prep: W/U -> [hi | hi | lo] bf16, itau ----------------
__global__ void k_prep(const float* __restrict__ W, const float* __restrict__ U,
                       const float* __restrict__ tau) {
  int idx = blockIdx.x * 256 + threadIdx.x;           // 2*512*1536 total
  const int HALF = 512 * 1536;
  int h = (idx >= HALF) ? 1 : 0;
  int j = idx - h * HALF;
  int n = j / 1536, k = j % 1536;
  int kk = k & 511, region = k >> 9;
  const float* src = h ? U : W;
  __nv_bfloat16* dst = h ? g_Ubig : g_Wbig;
  float w = src[n * 512 + kk];
  __nv_bfloat16 hi = __float2bfloat16(w);
  dst[j] = (region < 2) ? hi : __float2bfloat16(w - __bfloat162float(hi));
  if (idx < HID) g_itau[idx] = 1.0f / tau[idx];
}

// ---------------- fp32 microtile GEMM (k_in / k_head) ----------------
template <int K>
__device__ __forceinline__ void gemm_tile(const float* __restrict__ As,
                                          const float* __restrict__ Bg,
                                          int row0, int col0, float acc[4][16]) {
#pragma unroll
  for (int i = 0; i < 4; i++)
#pragma unroll
    for (int j = 0; j < 16; j++) acc[i][j] = 0.f;
#pragma unroll 1
  for (int k = 0; k < K; k += 4) {
    float4 a[4];
#pragma unroll
    for (int kk = 0; kk < 4; kk++)
      a[kk] = *reinterpret_cast<const float4*>(As + (k + kk) * 32 + row0);
    float4 bb[16];
#pragma unroll
    for (int j = 0; j < 16; j++)
      bb[j] = *reinterpret_cast<const float4*>(Bg + (size_t)(col0 + j) * K + k);
#pragma unroll
    for (int j = 0; j < 16; j++) {
      float bv[4] = {bb[j].x, bb[j].y, bb[j].z, bb[j].w};
#pragma unroll
      for (int kk = 0; kk < 4; kk++) {
        acc[0][j] = fmaf(a[kk].x, bv[kk], acc[0][j]);
        acc[1][j] = fmaf(a[kk].y, bv[kk], acc[1][j]);
        acc[2][j] = fmaf(a[kk].z, bv[kk], acc[2][j]);
        acc[3][j] = fmaf(a[kk].w, bv[kk], acc[3][j]);
      }
    }
  }
}

// u = x @ Wx^T + bx ; writes S0 (h0 = u) as bf16 hi/lo
__global__ void __launch_bounds__(256, 1)
k_in(const float* __restrict__ x, const float* __restrict__ Wx,
     const float* __restrict__ bx) {
  extern __shared__ float sm[];
  const int tid = threadIdx.x, b0 = blockIdx.x * 32;
  for (int idx = tid; idx < 32 * IN_DIM; idx += 256) {
    int m = idx >> 8, k = idx & 255;
    sm[k * 32 + m] = x[(size_t)(b0 + m) * IN_DIM + k];
  }
  __syncthreads();
  const int row0 = (tid & 7) * 4, col0 = (tid >> 3) * 16;
  float acc[4][16];
  gemm_tile<IN_DIM>(sm, Wx, row0, col0, acc);
#pragma unroll
  for (int j = 0; j < 16; j++) {
    float bxi = bx[col0 + j];
#pragma unroll
    for (int i = 0; i < 4; i++) {
      float v = acc[i][j] + bxi;
      size_t ix = (size_t)(b0 + row0 + i) * HID + col0 + j;
      __nv_bfloat16 hi = __float2bfloat16(v);
      g_S0h[ix] = hi;
      g_S0l[ix] = __float2bfloat16(v - __bfloat162float(hi));
    }
  }
}

// out = h @ Wf^T + bf  (h = S0 hi+lo)
__global__ void __launch_bounds__(256, 1)
k_head(const float* __restrict__ Wf, const float* __restrict__ bf,
       float* __restrict__ out) {
  extern __shared__ float sm[];
  const int tid = threadIdx.x, b0 = blockIdx.x * 32;
  for (int idx = tid; idx < 32 * HID; idx += 256) {
    int m = idx >> 9, k = idx & 511;
    size_t ix = (size_t)(b0 + m) * HID + k;
    sm[k * 32 + m] = __bfloat162float(g_S0h[ix]) + __bfloat162float(g_S0l[ix]);
  }
  __syncthreads();
  const int row0 = (tid & 7) * 4, oc0 = (tid >> 3) * 4;
  float acc[4][4];
#pragma unroll
  for (int i = 0; i < 4; i++)
#pragma unroll
    for (int j = 0; j < 4; j++) acc[i][j] = 0.f;
#pragma unroll 1
  for (int k = 0; k < HID; k += 4) {
    float4 a[4];
#pragma unroll
    for (int kk = 0; kk < 4; kk++)
      a[kk] = *reinterpret_cast<const float4*>(sm + (k + kk) * 32 + row0);
#pragma unroll
    for (int j = 0; j < 4; j++) {
      float4 bb = *reinterpret_cast<const float4*>(Wf + (size_t)(oc0 + j) * HID + k);
      float bv[4] = {bb.x, bb.y, bb.z, bb.w};
#pragma unroll
      for (int kk = 0; kk < 4; kk++) {
        acc[0][j] = fmaf(a[kk].x, bv[kk], acc[0][j]);
        acc[1][j] = fmaf(a[kk].y, bv[kk], acc[1][j]);
        acc[2][j] = fmaf(a[kk].z, bv[kk], acc[2][j]);
        acc[3][j] = fmaf(a[kk].w, bv[kk], acc[3][j]);
      }
    }
  }
#pragma unroll
  for (int i = 0; i < 4; i++) {
    float4 o = make_float4(acc[i][0] + bf[oc0 + 0], acc[i][1] + bf[oc0 + 1],
                           acc[i][2] + bf[oc0 + 2], acc[i][3] + bf[oc0 + 3]);
    *reinterpret_cast<float4*>(out + (size_t)(b0 + row0 + i) * OUT_DIM + oc0) = o;
  }
}

// ---------------- HMMA GEMM kernel (stages + drive) ----------------
// MODE 0..3: RK4 stage. MODE 4: drive = u @ U^T + b.
// 512 threads, 16 warps (4M x 4N), 128 rows/CTA, 4 n-chunks of 128.
// 3-stage cp.async pipeline, K chunk = 64 (24 chunks for K'=1536).
#define APITCH   144
#define ASTG     18432           /* 128*144 */
#define SSTRIDE  36864           /* A + B per stage */
#define NSTG     3
#define ST_SMEM  (NSTG * SSTRIDE)

__device__ __forceinline__ void ld_chunk(uint32_t stg_base, int b0, int n0, int kc,
                                         int tid, const __nv_bfloat16* shi,
                                         const __nv_bfloat16* slo,
                                         const __nv_bfloat16* Bmat) {
  const __nv_bfloat16* asrc = ((kc >> 3) == 1) ? slo : shi;
  const int k0 = (kc & 7) << 6;
  const int kg = kc << 6;
#pragma unroll
  for (int j = 0; j < 2; j++) {
    int i = tid + j * 512;
    int r = i >> 3, c = i & 7;
    cp16(stg_base + r * APITCH + c * 16,
         asrc + (((size_t)(b0 + r)) << 9) + k0 + c * 8);
    cp16(stg_base + ASTG + r * APITCH + c * 16,
         Bmat + (size_t)(n0 + r) * 1536 + kg + c * 8);
  }
}

template <int MODE>
__global__ void __launch_bounds__(512, 1) k_gemm(const float* __restrict__ bvec) {
  extern __shared__ __align__(128) char smem[];
  const uint32_t sb = smem_u32(smem);
  const int tid = threadIdx.x;
  const int lane = tid & 31, wid = tid >> 5;
  const int warp_m = wid & 3;            // 4 warps x 32 rows
  const int warp_n = wid >> 2;           // 4 warps x 32 cols
  const int b0 = blockIdx.x * 128;
  const int lr = lane & 15, lc = lane >> 4;

  const __nv_bfloat16* shi = (MODE == 4) ? g_S0h : Sh_ptr(MODE);
  const __nv_bfloat16* slo = (MODE == 4) ? g_S0l : Sl_ptr(MODE);
  const __nv_bfloat16* Bmat = (MODE == 4) ? g_Ubig : g_Wbig;
  __nv_bfloat16* dsth = (MODE == 4) ? g_S0h : Sh_ptr((MODE + 1) & 3);
  __nv_bfloat16* dstl = (MODE == 4) ? g_S0l : Sl_ptr((MODE + 1) & 3);

  const uint32_t a_off = (warp_m * 32 + lr) * APITCH + lc * 16;
  const uint32_t b_off = ASTG + (warp_n * 32 + lr) * APITCH + lc * 16;
  const uint32_t s_last = sb + 2 * SSTRIDE;

#pragma unroll 1
  for (int nc = 0; nc < 4; ++nc) {
    const int n0 = nc * 128;
    float acc[2][4][4];
#pragma unroll
    for (int i = 0; i < 2; i++)
#pragma unroll
      for (int j = 0; j < 4; j++)
#pragma unroll
        for (int q = 0; q < 4; q++) acc[i][j][q] = 0.f;

    ld_chunk(sb, b0, n0, 0, tid, shi, slo, Bmat); CP_COMMIT();
    ld_chunk(sb + SSTRIDE, b0, n0, 1, tid, shi, slo, Bmat); CP_COMMIT();

    uint32_t rd = sb, wr = sb + 2 * SSTRIDE;
#pragma unroll 1
    for (int kc = 0; kc < 24; ++kc) {
      CP_WAIT1();
      __syncthreads();
      const uint32_t ab = rd + a_off;
      const uint32_t bb = rd + b_off;
#pragma unroll
      for (int kk = 0; kk < 4; kk++) {
        uint32_t a[2][4], bfr[2][4];
        LDSM4(a[0][0], a[0][1], a[0][2], a[0][3], ab + kk * 32);
        LDSM4(a[1][0], a[1][1], a[1][2], a[1][3], ab + 16 * APITCH + kk * 32);
        LDSM4(bfr[0][0], bfr[0][1], bfr[0][2], bfr[0][3], bb + kk * 32);
        LDSM4(bfr[1][0], bfr[1][1], bfr[1][2], bfr[1][3], bb + 16 * APITCH + kk * 32);
#pragma unroll
        for (int fm = 0; fm < 2; fm++)
#pragma unroll
          for (int fn = 0; fn < 2; fn++) {
            MMA16816(acc[fm][2 * fn],     a[fm], bfr[fn][0], bfr[fn][2]);
            MMA16816(acc[fm][2 * fn + 1], a[fm], bfr[fn][1], bfr[fn][3]);
          }
      }
      if (kc < 22) ld_chunk(wr, b0, n0, kc + 2, tid, shi, slo, Bmat);
      CP_COMMIT();
      rd = (rd == s_last) ? sb : rd + SSTRIDE;
      wr = (wr == s_last) ? sb : wr + SSTRIDE;
    }

    // ---- fused epilogue on register fragments ----
    const int rq = lane >> 2, cq = (lane & 3) * 2;
#pragma unroll
    for (int fn = 0; fn < 4; fn++) {
      const int nn = n0 + warp_n * 32 + fn * 8 + cq;
#pragma unroll
      for (int fm = 0; fm < 2; fm++) {
#pragma unroll
        for (int half = 0; half < 2; half++) {
          const int r = b0 + warp_m * 32 + fm * 16 + rq + half * 8;
          const size_t ix = ((size_t)r << 9) + nn;
          const float c0 = acc[fm][fn][half * 2];
          const float c1 = acc[fm][fn][half * 2 + 1];
          if (MODE == 4) {
            float2 bv = *reinterpret_cast<const float2*>(bvec + nn);
            float2 o = make_float2(c0 + bv.x, c1 + bv.y);
            *reinterpret_cast<float2*>(g_drive + ix) = o;
          } else {
            const float2 it2 = *reinterpret_cast<const float2*>(g_itau + nn);
            float2 dr = *reinterpret_cast<const float2*>(g_drive + ix);
            __nv_bfloat162 sh2 = *reinterpret_cast<const __nv_bfloat162*>(shi + ix);
            __nv_bfloat162 sl2 = *reinterpret_cast<const __nv_bfloat162*>(slo + ix);
            float s0 = __bfloat162float(sh2.x) + __bfloat162float(sl2.x);
            float s1 = __bfloat162float(sh2.y) + __bfloat162float(sl2.y);
            float t0 = tanh_fast(c0 + dr.x);
            float t1 = tanh_fast(c1 + dr.y);
            float k0 = (t0 - s0) * it2.x;
            float k1 = (t1 - s1) * it2.y;
            float v0, v1;
            if (MODE == 0) {
              v0 = s0 + HDT * k0; v1 = s1 + HDT * k1;     // s2 = h + dt/2 k1
            } else {
              __nv_bfloat162 hh2 = *reinterpret_cast<const __nv_bfloat162*>(g_S0h + ix);
              __nv_bfloat162 hl2 = *reinterpret_cast<const __nv_bfloat162*>(g_S0l + ix);
              float h0 = __bfloat162float(hh2.x) + __bfloat162float(hl2.x);
              float h1 = __bfloat162float(hh2.y) + __bfloat162float(hl2.y);
              if (MODE == 1)      { v0 = h0 + HDT * k0; v1 = h1 + HDT * k1; }  // s3
              else if (MODE == 2) { v0 = h0 + DT * k0;  v1 = h1 + DT * k1;  }  // s4
              else {
                __nv_bfloat162 ah2 = *reinterpret_cast<const __nv_bfloat162*>(g_S1h + ix);
                __nv_bfloat162 al2 = *reinterpret_cast<const __nv_bfloat162*>(g_S1l + ix);
                __nv_bfloat162 bh2 = *reinterpret_cast<const __nv_bfloat162*>(g_S2h + ix);
                __nv_bfloat162 bl2 = *reinterpret_cast<const __nv_bfloat162*>(g_S2l + ix);
                float s20 = __bfloat162float(ah2.x) + __bfloat162float(al2.x);
                float s21 = __bfloat162float(ah2.y) + __bfloat162float(al2.y);
                float s30 = __bfloat162float(bh2.x) + __bfloat162float(bl2.x);
                float s31 = __bfloat162float(bh2.y) + __bfloat162float(bl2.y);
                v0 = h0 + (1.0f / 3.0f) * (s20 - h0) + (2.0f / 3.0f) * (s30 - h0)
                        + (1.0f / 3.0f) * (s0 - h0) + DT6 * k0;  // h_{n+1}
                v1 = h1 + (1.0f / 3.0f) * (s21 - h1) + (2.0f / 3.0f) * (s31 - h1)
                        + (1.0f / 3.0f) * (s1 - h1) + DT6 * k1;
              }
            }
            __nv_bfloat16 hi0 = __float2bfloat16(v0);
            __nv_bfloat16 hi1 = __float2bfloat16(v1);
            __nv_bfloat162 oh; oh.x = hi0; oh.y = hi1;
            __nv_bfloat162 ol;
            ol.x = __float2bfloat16(v0 - __bfloat162float(hi0));
            ol.y = __float2bfloat16(v1 - __bfloat162float(hi1));
            *reinterpret_cast<__nv_bfloat162*>(dsth + ix) = oh;
            *reinterpret_cast<__nv_bfloat162*>(dstl + ix) = ol;
          }
        }
      }
    }
    __syncthreads();   // stage buffers reused next nc
  }
}

// ---------------- launcher ----------------
extern "C" void kernel_launch(void* const* d_in, const int* in_sizes, int n_in,
                              void* d_out, int out_size) {
  (void)in_sizes; (void)n_in; (void)out_size;
  const float* x    = (const float*)d_in[0];
  const float* Wx   = (const float*)d_in[1];
  const float* bx   = (const float*)d_in[2];
  const float* W    = (const float*)d_in[3];
  const float* U    = (const float*)d_in[4];
  const float* bvec = (const float*)d_in[5];
  const float* tau  = (const float*)d_in[6];
  const float* Wf   = (const float*)d_in[7];
  const float* bf   = (const float*)d_in[8];
  float* out = (float*)d_out;

  cudaFuncSetAttribute(k_gemm<0>, cudaFuncAttributeMaxDynamicSharedMemorySize, ST_SMEM);
  cudaFuncSetAttribute(k_gemm<1>, cudaFuncAttributeMaxDynamicSharedMemorySize, ST_SMEM);
  cudaFuncSetAttribute(k_gemm<2>, cudaFuncAttributeMaxDynamicSharedMemorySize, ST_SMEM);
  cudaFuncSetAttribute(k_gemm<3>, cudaFuncAttributeMaxDynamicSharedMemorySize, ST_SMEM);
  cudaFuncSetAttribute(k_gemm<4>, cudaFuncAttributeMaxDynamicSharedMemorySize, ST_SMEM);
  cudaFuncSetAttribute(k_head,  cudaFuncAttributeMaxDynamicSharedMemorySize, 65536);
  cudaFuncSetAttribute(k_in,    cudaFuncAttributeMaxDynamicSharedMemorySize, 32768);

  k_prep<<<(2 * 512 * 1536) / 256, 256>>>(W, U, tau);
  k_in<<<BATCH / 32, 256, 32768>>>(x, Wx, bx);
  k_gemm<4><<<BATCH / 128, 512, ST_SMEM>>>(bvec);        // drive
  for (int step = 0; step < NSTEPS; ++step) {
    k_gemm<0><<<BATCH / 128, 512, ST_SMEM>>>(nullptr);
    k_gemm<1><<<BATCH / 128, 512, ST_SMEM>>>(nullptr);
    k_gemm<2><<<BATCH / 128, 512, ST_SMEM>>>(nullptr);
    k_gemm<3><<<BATCH / 128, 512, ST_SMEM>>>(nullptr);
  }
  k_head<<<BATCH / 32, 256, 65536>>>(Wf, bf, out);
}